// round 7
// baseline (speedup 1.0000x reference)
#include <cuda_runtime.h>
#include <cuda_bf16.h>
#include <stdint.h>
#include <math.h>

// SNN forward: 4 x (GEMM on binary spikes -> fused IIR+LIF scan), final layer
// also emits the output IIR filter. IIR/W commutation: coefficients are equal
// across features, so W @ IIR(s) == IIR(W @ s); GEMMs consume raw spike trains.
//
// R6: (a) GEMM moved to tensor cores: fp32 weights split into 3 bf16 planes
//         (error ~2^-27, below fp32 reorder noise -> spikes unchanged),
//         spikes are exact in bf16. mma.sync.m16n8k16, fp32 accumulate.
//     (b) scans: 64 rows / 64-thread block -> 200-500 blocks (full chip).

#define TT 300
#define NB 64

// scratch (device globals: no allocation allowed in kernel_launch)
__device__ float g_cur[NB * 500 * TT];
__device__ float g_s1 [NB * 500 * TT];
__device__ float g_s2 [NB * 200 * TT];
__device__ float g_s3 [NB * 500 * TT];

// ---------------------------------------------------------------------------
// Batched GEMM, tensor cores: C[b,m,t] = sum_k W[m,k] * S[b,k,t]
// W fp32 split on the fly into 3 bf16 planes; S (binary) cast to bf16 exactly.
// grid = (ceil(TT/64), ceil(M/128), NB), block = 256 (8 warps: 4 M x 2 N).
// Warp tile 32(M) x 32(N) = 2 m-frags x 4 n-frags of m16n8k16.
// ---------------------------------------------------------------------------
template <int M, int K>
__global__ void __launch_bounds__(256)
gemm_bf16_kernel(const float* __restrict__ S,   // [NB, K, TT]
                 const float* __restrict__ W,   // [M, K] fp32
                 float* __restrict__ C)         // [NB, M, TT]
{
    // pitches of 40 halves: verified conflict-free for the fragment LDS reads
    __shared__ __nv_bfloat16 A_sm[3][128][40];  // [split][m][k]
    __shared__ __nv_bfloat16 B_sm[64][40];      // [n(t)][k]  (transposed stage)

    const int b   = blockIdx.z;
    const int bm  = blockIdx.y * 128;
    const int t0  = blockIdx.x * 64;
    const int tid = threadIdx.x;
    const int lane = tid & 31, wid = tid >> 5;
    const int g  = lane >> 2;        // group id (0..7)
    const int t4 = lane & 3;         // thread-in-group (0..3)
    const int wm = (wid & 3) * 32;   // warp M offset in tile
    const int wn = (wid >> 2) * 32;  // warp N offset in tile

    const float* Sb = S + (size_t)b * K * TT;

    float acc[2][4][4];
#pragma unroll
    for (int mf = 0; mf < 2; ++mf)
#pragma unroll
        for (int nf = 0; nf < 4; ++nf)
#pragma unroll
            for (int i = 0; i < 4; ++i) acc[mf][nf][i] = 0.0f;

    const int NC = (K + 31) / 32;
    for (int kc = 0; kc < NC; ++kc) {
        const int k0 = kc * 32;

        // --- stage A: load W chunk (128 x 32 fp32), 3-way bf16 split ---
#pragma unroll
        for (int r = 0; r < 16; ++r) {
            int idx = tid + r * 256;
            int m = idx >> 5, kk = idx & 31;           // lane == kk: coalesced
            float w = 0.0f;
            if (bm + m < M && k0 + kk < K) w = W[(size_t)(bm + m) * K + k0 + kk];
            __nv_bfloat16 h0 = __float2bfloat16(w);
            float r1 = w - __bfloat162float(h0);
            __nv_bfloat16 h1 = __float2bfloat16(r1);
            float r2 = r1 - __bfloat162float(h1);
            __nv_bfloat16 h2 = __float2bfloat16(r2);
            A_sm[0][m][kk] = h0;
            A_sm[1][m][kk] = h1;
            A_sm[2][m][kk] = h2;
        }
        // --- stage B: load S chunk (32 x 64), store transposed [n][k] ---
#pragma unroll
        for (int r = 0; r < 8; ++r) {
            int idx = tid + r * 256;
            int kk = idx >> 6, t = idx & 63;           // t coalesced per warp
            float v = 0.0f;
            if (k0 + kk < K && t0 + t < TT) v = Sb[(size_t)(k0 + kk) * TT + t0 + t];
            B_sm[t][kk] = __float2bfloat16(v);         // 0/1: exact
        }
        __syncthreads();

#pragma unroll
        for (int ks = 0; ks < 32; ks += 16) {
            // B fragments (shared across the 3 splits)
            uint32_t Bf[4][2];
#pragma unroll
            for (int nf = 0; nf < 4; ++nf) {
                int n = wn + nf * 8 + g;
                Bf[nf][0] = *(const uint32_t*)&B_sm[n][ks + 2 * t4];
                Bf[nf][1] = *(const uint32_t*)&B_sm[n][ks + 2 * t4 + 8];
            }
#pragma unroll
            for (int s = 0; s < 3; ++s) {
#pragma unroll
                for (int mf = 0; mf < 2; ++mf) {
                    int mr = wm + mf * 16;
                    uint32_t a0 = *(const uint32_t*)&A_sm[s][mr + g    ][ks + 2 * t4];
                    uint32_t a1 = *(const uint32_t*)&A_sm[s][mr + 8 + g][ks + 2 * t4];
                    uint32_t a2 = *(const uint32_t*)&A_sm[s][mr + g    ][ks + 2 * t4 + 8];
                    uint32_t a3 = *(const uint32_t*)&A_sm[s][mr + 8 + g][ks + 2 * t4 + 8];
#pragma unroll
                    for (int nf = 0; nf < 4; ++nf) {
                        asm volatile(
                            "mma.sync.aligned.m16n8k16.row.col.f32.bf16.bf16.f32 "
                            "{%0,%1,%2,%3}, {%4,%5,%6,%7}, {%8,%9}, {%0,%1,%2,%3};"
                            : "+f"(acc[mf][nf][0]), "+f"(acc[mf][nf][1]),
                              "+f"(acc[mf][nf][2]), "+f"(acc[mf][nf][3])
                            : "r"(a0), "r"(a1), "r"(a2), "r"(a3),
                              "r"(Bf[nf][0]), "r"(Bf[nf][1]));
                    }
                }
            }
        }
        __syncthreads();
    }

    // --- epilogue: c0,c1 at (m=g, t=2*t4,+1); c2,c3 at m=g+8. t even, TT even.
    float* Cb = C + (size_t)b * M * TT;
#pragma unroll
    for (int mf = 0; mf < 2; ++mf) {
#pragma unroll
        for (int nf = 0; nf < 4; ++nf) {
            int t = t0 + wn + nf * 8 + 2 * t4;
            if (t < TT) {
                int m0 = bm + wm + mf * 16 + g;
                if (m0 < M)
                    *(float2*)&Cb[(size_t)m0 * TT + t] =
                        make_float2(acc[mf][nf][0], acc[mf][nf][1]);
                int m1 = m0 + 8;
                if (m1 < M)
                    *(float2*)&Cb[(size_t)m1 * TT + t] =
                        make_float2(acc[mf][nf][2], acc[mf][nf][3]);
            }
        }
    }
}

// ---------------------------------------------------------------------------
// Fused temporal scan: 64 rows per 64-thread block, time chunks of 150 staged
// through smem (pitch 151: conflict-free). Coalesced load/store; each thread
// scans its private smem row.
//   y[t]  = a1*y[t-1] + a2*y[t-2] + b0*cur[t]
//   v = y + bias + reset ; s = (v >= 1) ; reset = reset*em - s
// ---------------------------------------------------------------------------
__global__ void __launch_bounds__(64)
scan_lif(const float* __restrict__ Cur,
         const float* __restrict__ a1p, const float* __restrict__ a2p,
         const float* __restrict__ bp,  const float* __restrict__ bias,
         float* __restrict__ Sout, int F, float em)
{
    __shared__ float tile[64][151];
    const int row0 = blockIdx.x * 64;
    const int row  = row0 + threadIdx.x;
    const int o    = row % F;
    const int lane = threadIdx.x & 31, w = threadIdx.x >> 5;
    const float a1 = a1p[0], a2 = a2p[0], b0 = bp[0], bo = bias[o];

    float y1 = 0.0f, y2 = 0.0f, reset = 0.0f;

    for (int t0 = 0; t0 < TT; t0 += 150) {
#pragma unroll 4
        for (int rr = 0; rr < 32; ++rr) {
            const float* src = Cur + (size_t)(row0 + w * 32 + rr) * TT + t0;
            for (int j = lane; j < 150; j += 32) tile[w * 32 + rr][j] = src[j];
        }
        __syncthreads();

#pragma unroll 10
        for (int t = 0; t < 150; ++t) {
            float c = tile[threadIdx.x][t];
            float y = a1 * y1 + a2 * y2 + b0 * c;
            y2 = y1; y1 = y;
            float v = y + bo + reset;
            float s = (v >= 1.0f) ? 1.0f : 0.0f;
            reset = reset * em - s;
            tile[threadIdx.x][t] = s;
        }
        __syncthreads();

#pragma unroll 4
        for (int rr = 0; rr < 32; ++rr) {
            float* dst = Sout + (size_t)(row0 + w * 32 + rr) * TT + t0;
            for (int j = lane; j < 150; j += 32) dst[j] = tile[w * 32 + rr][j];
        }
        __syncthreads();
    }
}

// Final layer: also runs the fixed output dual-exp IIR on the spikes.
// Same tile reused: scan->store spikes->in-place filt scan->store filt.
__global__ void __launch_bounds__(64)
scan_lif_final(const float* __restrict__ Cur,
               const float* __restrict__ a1p, const float* __restrict__ a2p,
               const float* __restrict__ bp,  const float* __restrict__ bias,
               float* __restrict__ Sout, float* __restrict__ Filt,
               int F, float em, float fa1, float fa2, float fb)
{
    __shared__ float tile[64][151];
    const int row0 = blockIdx.x * 64;
    const int row  = row0 + threadIdx.x;
    const int o    = row % F;
    const int lane = threadIdx.x & 31, w = threadIdx.x >> 5;
    const float a1 = a1p[0], a2 = a2p[0], b0 = bp[0], bo = bias[o];

    float y1 = 0.0f, y2 = 0.0f, reset = 0.0f;
    float f1 = 0.0f, f2 = 0.0f;

    for (int t0 = 0; t0 < TT; t0 += 150) {
#pragma unroll 4
        for (int rr = 0; rr < 32; ++rr) {
            const float* src = Cur + (size_t)(row0 + w * 32 + rr) * TT + t0;
            for (int j = lane; j < 150; j += 32) tile[w * 32 + rr][j] = src[j];
        }
        __syncthreads();

#pragma unroll 10
        for (int t = 0; t < 150; ++t) {
            float c = tile[threadIdx.x][t];
            float y = a1 * y1 + a2 * y2 + b0 * c;
            y2 = y1; y1 = y;
            float v = y + bo + reset;
            float s = (v >= 1.0f) ? 1.0f : 0.0f;
            reset = reset * em - s;
            tile[threadIdx.x][t] = s;
        }
        __syncthreads();

#pragma unroll 4
        for (int rr = 0; rr < 32; ++rr) {
            float* dst = Sout + (size_t)(row0 + w * 32 + rr) * TT + t0;
            for (int j = lane; j < 150; j += 32) dst[j] = tile[w * 32 + rr][j];
        }
        __syncthreads();

        // in-place output filter on the spikes still resident in the tile
#pragma unroll 10
        for (int t = 0; t < 150; ++t) {
            float s = tile[threadIdx.x][t];
            float f = fa1 * f1 + fa2 * f2 + fb * s;
            f2 = f1; f1 = f;
            tile[threadIdx.x][t] = f;
        }
        __syncthreads();

#pragma unroll 4
        for (int rr = 0; rr < 32; ++rr) {
            float* dst = Filt + (size_t)(row0 + w * 32 + rr) * TT + t0;
            for (int j = lane; j < 150; j += 32) dst[j] = tile[w * 32 + rr][j];
        }
        __syncthreads();
    }
}

// ---------------------------------------------------------------------------
extern "C" void kernel_launch(void* const* d_in, const int* in_sizes, int n_in,
                              void* d_out, int out_size)
{
    const float* inputs = (const float*)d_in[0];
    const float* a1_1 = (const float*)d_in[1];
    const float* a2_1 = (const float*)d_in[2];
    const float* b_1  = (const float*)d_in[3];
    const float* W1   = (const float*)d_in[4];
    const float* bias1= (const float*)d_in[5];
    const float* a1_2 = (const float*)d_in[6];
    const float* a2_2 = (const float*)d_in[7];
    const float* b_2  = (const float*)d_in[8];
    const float* W2   = (const float*)d_in[9];
    const float* bias2= (const float*)d_in[10];
    const float* a1_3 = (const float*)d_in[11];
    const float* a2_3 = (const float*)d_in[12];
    const float* b_3  = (const float*)d_in[13];
    const float* W3   = (const float*)d_in[14];
    const float* bias3= (const float*)d_in[15];
    const float* a1_4 = (const float*)d_in[16];
    const float* a2_4 = (const float*)d_in[17];
    const float* b_4  = (const float*)d_in[18];
    const float* W4   = (const float*)d_in[19];
    const float* bias4= (const float*)d_in[20];

    float* out      = (float*)d_out;
    float* s4_out   = out;                              // [64, 300, 300]
    float* filt_out = out + (size_t)NB * 300 * TT;      // [64, 300, 300]

    float *cur, *s1, *s2, *s3;
    cudaGetSymbolAddress((void**)&cur, g_cur);
    cudaGetSymbolAddress((void**)&s1,  g_s1);
    cudaGetSymbolAddress((void**)&s2,  g_s2);
    cudaGetSymbolAddress((void**)&s3,  g_s3);

    // Output-filter constants (float64 -> float32 path, matching reference)
    const double em_d = exp(-1.0 / 8.0), es_d = exp(-1.0 / 2.0);
    const float em  = (float)em_d;
    const float fa1 = (float)(em_d + es_d);
    const float fa2 = (float)(-(em_d * es_d));
    const float fb  = (float)((8.0 / 6.0) * (em_d - es_d));

    // Layer 1: 300 -> 500
    gemm_bf16_kernel<500, 300><<<dim3(5, 4, NB), 256>>>(inputs, W1, cur);
    scan_lif<<<NB * 500 / 64, 64>>>(cur, a1_1, a2_1, b_1, bias1, s1, 500, em);

    // Layer 2: 500 -> 200
    gemm_bf16_kernel<200, 500><<<dim3(5, 2, NB), 256>>>(s1, W2, cur);
    scan_lif<<<NB * 200 / 64, 64>>>(cur, a1_2, a2_2, b_2, bias2, s2, 200, em);

    // Layer 3: 200 -> 500
    gemm_bf16_kernel<500, 200><<<dim3(5, 4, NB), 256>>>(s2, W3, cur);
    scan_lif<<<NB * 500 / 64, 64>>>(cur, a1_3, a2_3, b_3, bias3, s3, 500, em);

    // Layer 4: 500 -> 300, writes s4 + output filter directly into d_out
    gemm_bf16_kernel<300, 500><<<dim3(5, 3, NB), 256>>>(s3, W4, cur);
    scan_lif_final<<<NB * 300 / 64, 64>>>(cur, a1_4, a2_4, b_4, bias4,
                                          s4_out, filt_out, 300, em,
                                          fa1, fa2, fb);
}